// round 3
// baseline (speedup 1.0000x reference)
#include <cuda_runtime.h>

#define D     1024
#define HD    4096
#define LNUM  12
#define VOCAB 50257
#define NT    512
#define NW    16
#define NSLOT 3
#define SLOT_F 1024   // floats per pipeline slot (4KB)

// ---------------- global scratch ----------------
__device__ float g_x[D];
__device__ float g_k[D];
__device__ float g_v[D];
__device__ float g_r[D];
__device__ float g_k2[HD];
__device__ float g_r2[D];

// ---------------- 2-level software grid barrier ----------------
__device__ unsigned g_bar_gen = 0;
__device__ unsigned g_leaf[8 * 128];
__device__ unsigned g_root = 0;

__device__ __forceinline__ void grid_barrier(int nb) {
    __syncthreads();
    if (threadIdx.x == 0) {
        __threadfence();
        unsigned gen = *((volatile unsigned*)&g_bar_gen);
        int leaf = blockIdx.x & 7;
        unsigned target = (unsigned)((nb >> 3) + ((blockIdx.x & 7) < (nb & 7) ? 1 : 0));
        if (atomicAdd(&g_leaf[leaf * 128], 1u) == target - 1u) {
            g_leaf[leaf * 128] = 0;
            __threadfence();
            if (atomicAdd(&g_root, 1u) == 7u) {
                g_root = 0;
                __threadfence();
                atomicAdd(&g_bar_gen, 1u);
            }
        }
        while (*((volatile unsigned*)&g_bar_gen) == gen) { }
        __threadfence();
    }
    __syncthreads();
}

// ---------------- block-wide sum ----------------
__device__ __forceinline__ float block_sum(float v, float* sred) {
    int lane = threadIdx.x & 31, wid = threadIdx.x >> 5;
    #pragma unroll
    for (int o = 16; o; o >>= 1) v += __shfl_xor_sync(0xffffffffu, v, o);
    if (lane == 0) sred[wid] = v;
    __syncthreads();
    float t = 0.f;
    if (wid == 0) {
        t = (lane < NW) ? sred[lane] : 0.f;
        #pragma unroll
        for (int o = 8; o; o >>= 1) t += __shfl_xor_sync(0xffffffffu, t, o);
        if (lane == 0) sred[0] = t;
    }
    __syncthreads();
    float r = sred[0];
    __syncthreads();
    return r;
}

// ---------------- cp.async helpers ----------------
__device__ __forceinline__ void cp16(float* s, const float4* g) {
    unsigned sa = (unsigned)__cvta_generic_to_shared(s);
    asm volatile("cp.async.cg.shared.global [%0], [%1], 16;\n" :: "r"(sa), "l"(g));
}
__device__ __forceinline__ void cp_commit() {
    asm volatile("cp.async.commit_group;\n" ::: "memory");
}
template<int N> __device__ __forceinline__ void cp_wait() {
    asm volatile("cp.async.wait_group %0;\n" :: "n"(N) : "memory");
}

// ---------------- warp-private pipelined matvec ----------------
// Items are 4KB row-chunks; C consecutive items form one logical row.
template<class GetW, class GetV, class Fin>
__device__ __forceinline__ void mv_pipe(int nItems, int C, int pre, float* wslot,
                                        GetW getW, GetV getV, Fin fin) {
    const int lane = threadIdx.x & 31;
    float ax = 0.f, ay = 0.f, az = 0.f, aw = 0.f;
    for (int i = 0; i < nItems + 2; i++) {
        if (i >= pre && i < nItems) {
            const float4* g4 = (const float4*)getW(i);
            float* slot = wslot + (i % NSLOT) * SLOT_F;
            #pragma unroll
            for (int u = 0; u < 8; u++)
                cp16(slot + (u * 32 + lane) * 4, g4 + u * 32 + lane);
            cp_commit();
        }
        int j = i - 2;
        if (j >= 0) {
            int rem = nItems - 1 - j;     // groups committed after group j
            if (rem >= 2)      cp_wait<2>();
            else if (rem == 1) cp_wait<1>();
            else               cp_wait<0>();
            const float4* s4 = (const float4*)(wslot + (j % NSLOT) * SLOT_F);
            const float4* v4 = getV(j);
            #pragma unroll
            for (int u = 0; u < 8; u++) {
                float4 a = s4[u * 32 + lane];
                float4 b = v4[u * 32 + lane];
                ax = fmaf(a.x, b.x, ax);
                ay = fmaf(a.y, b.y, ay);
                az = fmaf(a.z, b.z, az);
                aw = fmaf(a.w, b.w, aw);
            }
            if ((j % C) == (C - 1)) {
                float t = (ax + ay) + (az + aw);
                #pragma unroll
                for (int o = 16; o; o >>= 1) t += __shfl_xor_sync(0xffffffffu, t, o);
                fin(j / C, t);
                ax = ay = az = aw = 0.f;
            }
        }
    }
}

// pre-issue first (up to 2) items of the next stage (hides barrier + latency)
template<class GetW>
__device__ __forceinline__ int mv_pre(int nItems, float* wslot, GetW getW) {
    const int lane = threadIdx.x & 31;
    int p = nItems < 2 ? nItems : 2;
    for (int i = 0; i < p; i++) {
        const float4* g4 = (const float4*)getW(i);
        float* slot = wslot + (i % NSLOT) * SLOT_F;
        #pragma unroll
        for (int u = 0; u < 8; u++)
            cp16(slot + (u * 32 + lane) * 4, g4 + u * 32 + lane);
        cp_commit();
    }
    return p;
}

__global__ __launch_bounds__(NT, 1) void rwkv_persistent(
    const int*   __restrict__ ctx,
    const float* __restrict__ st_in,
    const float* __restrict__ emb,
    const float* __restrict__ ln0,
    const float* __restrict__ ln1,
    const float* __restrict__ ln2,
    const float* __restrict__ lnout,
    const float* __restrict__ tmk,
    const float* __restrict__ tmv,
    const float* __restrict__ tmr,
    const float* __restrict__ tfirst,
    const float* __restrict__ tdecay,
    const float* __restrict__ kw,
    const float* __restrict__ vw,
    const float* __restrict__ rw,
    const float* __restrict__ ow,
    const float* __restrict__ ftmk,
    const float* __restrict__ ftmr,
    const float* __restrict__ fkw,
    const float* __restrict__ fvw,
    const float* __restrict__ frw,
    const float* __restrict__ head,
    float* __restrict__ out,
    int nb)
{
    extern __shared__ float smem[];
    float* vecS = smem + NW * NSLOT * SLOT_F;   // 4096 floats
    float* sred = vecS + HD;                    // NW floats

    const int tid  = threadIdx.x;
    const int lane = tid & 31;
    const int wid  = tid >> 5;
    float* wslot   = smem + wid * NSLOT * SLOT_F;
    const int gw   = blockIdx.x * NW + wid;
    const int nwG  = nb * NW;

    float* out_logits = out;
    float* out_state  = out + VOCAB;

    auto nown = [&](int R) { return gw < R ? (R - 1 - gw) / nwG + 1 : 0; };
    const int nA = nown(3 * D);
    const int nB = nown(D);
    const int nC = nown(HD + D);
    const int nD = nown(D) * 4;
    const int nH = nown(VOCAB);

    // mutable weight pointers captured by the stage lambdas
    const float *kwl, *vwl, *rwl, *owl, *fkwl, *frwl, *fvwl;
    const float *st_l;
    float *ost_l;

    auto getW_A = [&](int i) {
        int row = gw + i * nwG;
        if (row < D)       return kwl + (size_t)row * D;
        if (row < 2 * D)   return vwl + (size_t)(row - D) * D;
        return rwl + (size_t)(row - 2 * D) * D;
    };
    auto getV_A = [&](int i) {
        int row = gw + i * nwG;
        return (const float4*)(vecS + (row < D ? 0 : (row < 2 * D ? D : 2 * D)));
    };
    auto fin_A = [&](int r, float t) {
        if (lane == 0) {
            int row = gw + r * nwG;
            if (row < D)          g_k[row] = t;
            else if (row < 2 * D) g_v[row - D] = t;
            else                  g_r[row - 2 * D] = t;
        }
    };
    auto getW_B = [&](int i) { return owl + (size_t)(gw + i * nwG) * D; };
    auto getV_B = [&](int i) { (void)i; return (const float4*)vecS; };
    auto fin_B  = [&](int r, float t) {
        if (lane == 0) { int row = gw + r * nwG; g_x[row] += t; }
    };
    auto getW_C = [&](int i) {
        int row = gw + i * nwG;
        if (row < HD) return fkwl + (size_t)row * D;
        return frwl + (size_t)(row - HD) * D;
    };
    auto getV_C = [&](int i) {
        int row = gw + i * nwG;
        return (const float4*)(vecS + (row < HD ? 0 : D));
    };
    auto fin_C = [&](int r, float t) {
        if (lane == 0) {
            int row = gw + r * nwG;
            if (row < HD) { t = fmaxf(t, 0.f); g_k2[row] = t * t; }
            else g_r2[row - HD] = t;
        }
    };
    auto getW_D = [&](int i) {
        int row = gw + (i >> 2) * nwG;
        return fvwl + (size_t)row * HD + (size_t)(i & 3) * SLOT_F;
    };
    auto getV_D = [&](int i) { return (const float4*)(vecS + (i & 3) * SLOT_F); };
    auto getW_H = [&](int i) { return head + (size_t)(gw + i * nwG) * D; };
    auto getV_H = [&](int i) { (void)i; return (const float4*)vecS; };
    auto fin_H  = [&](int r, float t) {
        if (lane == 0) out_logits[gw + r * nwG] = t;
    };

    // ---------- pre-issue layer-0 stage-A weights, compute embedding ----------
    kwl = kw; vwl = vw; rwl = rw;
    int preA = mv_pre(nA, wslot, getW_A);
    int preB = 0, preC = 0, preD = 0, preH = 0;

    if (blockIdx.x == 0) {
        const float* e = emb + (size_t)ctx[0] * D;
        float ss = 0.f;
        for (int j = tid; j < D; j += NT) { float t = e[j]; ss += t * t; }
        ss = block_sum(ss, sred);
        float inv = rsqrtf(ss * (1.f / D) + 1e-5f);
        for (int j = tid; j < D; j += NT) g_x[j] = e[j] * inv * ln0[j];
    }
    grid_barrier(nb);

    for (int l = 0; l < LNUM; l++) {
        st_l  = st_in     + (size_t)l * 5 * D;
        ost_l = out_state + (size_t)l * 5 * D;

        // ---------- stage A: rms + token-mix prep; k/v/r matvecs ----------
        {
            float ss = 0.f;
            for (int j = tid; j < D; j += NT) { float t = g_x[j]; ss += t * t; }
            ss = block_sum(ss, sred);
            float inv = rsqrtf(ss * (1.f / D) + 1e-5f);
            const float* l1 = ln1 + l * D;
            const float* mk = tmk + l * D;
            const float* mv = tmv + l * D;
            const float* mr = tmr + l * D;
            for (int j = tid; j < D; j += NT) {
                float xxj = g_x[j] * inv * l1[j];
                float sa  = st_l[D + j];
                float a_ = mk[j]; vecS[j]         = xxj * a_ + sa * (1.f - a_);
                float b_ = mv[j]; vecS[D + j]     = xxj * b_ + sa * (1.f - b_);
                float c_ = mr[j]; vecS[2 * D + j] = xxj * c_ + sa * (1.f - c_);
                if (blockIdx.x == 0) ost_l[D + j] = xxj;
            }
            __syncthreads();
            mv_pipe(nA, 1, preA, wslot, getW_A, getV_A, fin_A);
        }
        owl = ow + (size_t)l * D * D;
        preB = mv_pre(nB, wslot, getW_B);
        grid_barrier(nb);

        // ---------- stage B: WKV elementwise; ow matvec ----------
        {
            const float* tfl = tfirst + l * D;
            const float* tdl = tdecay + l * D;
            for (int j = tid; j < D; j += NT) {
                float k  = g_k[j], v = g_v[j], rr = g_r[j];
                float aa = st_l[2 * D + j], bb = st_l[3 * D + j], pp = st_l[4 * D + j];
                float ww = tfl[j] + k;
                float p  = fmaxf(pp, ww);
                float e1 = __expf(pp - p), e2 = __expf(ww - p);
                float a  = e1 * aa + e2 * v;
                float b  = e1 * bb + e2;
                float sr = 1.f / (1.f + __expf(-rr));
                vecS[j] = sr * (a / b);
                if (blockIdx.x == 0) {
                    float ww2 = pp + tdl[j];
                    float p2  = fmaxf(ww2, k);
                    float e1b = __expf(ww2 - p2), e2b = __expf(k - p2);
                    ost_l[2 * D + j] = e1b * aa + e2b * v;
                    ost_l[3 * D + j] = e1b * bb + e2b;
                    ost_l[4 * D + j] = p2;
                }
            }
            __syncthreads();
            mv_pipe(nB, 1, preB, wslot, getW_B, getV_B, fin_B);
        }
        fkwl = fkw + (size_t)l * HD * D;
        frwl = frw + (size_t)l * D * D;
        preC = mv_pre(nC, wslot, getW_C);
        grid_barrier(nb);

        // ---------- stage C: rms2 + channel-mix prep; fkw/frw matvecs ----------
        {
            float ss = 0.f;
            for (int j = tid; j < D; j += NT) { float t = g_x[j]; ss += t * t; }
            ss = block_sum(ss, sred);
            float inv = rsqrtf(ss * (1.f / D) + 1e-5f);
            const float* l2l = ln2  + l * D;
            const float* fmk = ftmk + l * D;
            const float* fmr = ftmr + l * D;
            for (int j = tid; j < D; j += NT) {
                float yyj = g_x[j] * inv * l2l[j];
                float ff  = st_l[j];
                float a_ = fmk[j]; vecS[j]     = yyj * a_ + ff * (1.f - a_);
                float b_ = fmr[j]; vecS[D + j] = yyj * b_ + ff * (1.f - b_);
                if (blockIdx.x == 0) ost_l[j] = yyj;
            }
            __syncthreads();
            mv_pipe(nC, 1, preC, wslot, getW_C, getV_C, fin_C);
        }
        fvwl = fvw + (size_t)l * D * HD;
        preD = mv_pre(nD, wslot, getW_D);
        grid_barrier(nb);

        // ---------- stage D: x = (x + sigmoid(r2) * (fvw @ k2)) * sc ----------
        {
            for (int j = tid; j < HD; j += NT) vecS[j] = g_k2[j];
            __syncthreads();
            const float sc = ((l + 1) % 6 == 0) ? 0.5f : 1.0f;
            auto fin_D = [&](int r, float t) {
                if (lane == 0) {
                    int row = gw + r * nwG;
                    float sr = 1.f / (1.f + __expf(-g_r2[row]));
                    g_x[row] = (g_x[row] + sr * t) * sc;
                }
            };
            mv_pipe(nD, 4, preD, wslot, getW_D, getV_D, fin_D);
        }
        if (l < LNUM - 1) {
            kwl = kw + (size_t)(l + 1) * D * D;
            vwl = vw + (size_t)(l + 1) * D * D;
            rwl = rw + (size_t)(l + 1) * D * D;
            preA = mv_pre(nA, wslot, getW_A);
        } else {
            preH = mv_pre(nH, wslot, getW_H);
        }
        grid_barrier(nb);
    }

    // ---------- head ----------
    {
        float ss = 0.f;
        for (int j = tid; j < D; j += NT) { float t = g_x[j]; ss += t * t; }
        ss = block_sum(ss, sred);
        float inv = rsqrtf(ss * (1.f / D) + 1e-5f);
        for (int j = tid; j < D; j += NT) vecS[j] = g_x[j] * inv * lnout[j];
        __syncthreads();
        mv_pipe(nH, 1, preH, wslot, getW_H, getV_H, fin_H);
    }
}

extern "C" void kernel_launch(void* const* d_in, const int* in_sizes, int n_in,
                              void* d_out, int out_size) {
    (void)in_sizes; (void)n_in; (void)out_size;
    int nb = 0;
    cudaDeviceGetAttribute(&nb, cudaDevAttrMultiProcessorCount, 0);
    if (nb <= 0) nb = 148;
    if (nb > 1024) nb = 1024;

    const int smem_bytes = (NW * NSLOT * SLOT_F + HD + 64) * (int)sizeof(float);
    cudaFuncSetAttribute(rwkv_persistent,
                         cudaFuncAttributeMaxDynamicSharedMemorySize, smem_bytes);

    rwkv_persistent<<<nb, NT, smem_bytes>>>(
        (const int*)  d_in[0],   // ctx
        (const float*)d_in[1],   // state
        (const float*)d_in[2],   // emb
        (const float*)d_in[3],   // ln0_w
        (const float*)d_in[4],   // ln1_w
        (const float*)d_in[5],   // ln2_w
        (const float*)d_in[6],   // lnout_w
        (const float*)d_in[7],   // att_tmk
        (const float*)d_in[8],   // att_tmv
        (const float*)d_in[9],   // att_tmr
        (const float*)d_in[10],  // att_tfirst
        (const float*)d_in[11],  // att_tdecay
        (const float*)d_in[12],  // att_kw
        (const float*)d_in[13],  // att_vw
        (const float*)d_in[14],  // att_rw
        (const float*)d_in[15],  // att_ow
        (const float*)d_in[16],  // ffn_tmk
        (const float*)d_in[17],  // ffn_tmr
        (const float*)d_in[18],  // ffn_kw
        (const float*)d_in[19],  // ffn_vw
        (const float*)d_in[20],  // ffn_rw
        (const float*)d_in[21],  // head
        (float*)d_out, nb);
}

// round 4
// speedup vs baseline: 1.0264x; 1.0264x over previous
#include <cuda_runtime.h>
#include <cstdint>

#define D      1024
#define HD     4096
#define LNUM   12
#define VOCAB  50257
#define NT     512
#define NWP    16
#define S_RING 12
#define SLOT_B 16384
#define SLOT_F4 1024          // float4 per slot

#define NC_A 768              // 3*1024 rows / 4
#define NC_B 512              // 1024 rows / 2
#define NC_C 1280             // (4096+1024) rows / 4
#define NC_D 1024             // 1024 rows, 1 per chunk (16KB rows)
#define NC_H 12565            // ceil(50257/4)

// ---------------- global scratch ----------------
__device__ float g_x[D];
__device__ float g_k[D];
__device__ float g_v[D];
__device__ float g_r[D];
__device__ float g_k2[HD];
__device__ float g_r2[D];

// ---------------- 2-level software grid barrier ----------------
__device__ unsigned g_bar_gen = 0;
__device__ unsigned g_leaf[8 * 128];
__device__ unsigned g_root = 0;

__device__ __forceinline__ void grid_barrier(int nb) {
    __syncthreads();
    if (threadIdx.x == 0) {
        __threadfence();
        unsigned gen = *((volatile unsigned*)&g_bar_gen);
        int leaf = blockIdx.x & 7;
        unsigned target = (unsigned)((nb >> 3) + ((blockIdx.x & 7) < (nb & 7) ? 1 : 0));
        if (atomicAdd(&g_leaf[leaf * 128], 1u) == target - 1u) {
            g_leaf[leaf * 128] = 0;
            __threadfence();
            if (atomicAdd(&g_root, 1u) == 7u) {
                g_root = 0;
                __threadfence();
                atomicAdd(&g_bar_gen, 1u);
            }
        }
        while (*((volatile unsigned*)&g_bar_gen) == gen) { }
        __threadfence();
    }
    __syncthreads();
}

// ---------------- block-wide sum ----------------
__device__ __forceinline__ float block_sum(float v, float* sred) {
    int lane = threadIdx.x & 31, wid = threadIdx.x >> 5;
    #pragma unroll
    for (int o = 16; o; o >>= 1) v += __shfl_xor_sync(0xffffffffu, v, o);
    if (lane == 0) sred[wid] = v;
    __syncthreads();
    float t = 0.f;
    if (wid == 0) {
        t = (lane < NWP) ? sred[lane] : 0.f;
        #pragma unroll
        for (int o = 8; o; o >>= 1) t += __shfl_xor_sync(0xffffffffu, t, o);
        if (lane == 0) sred[0] = t;
    }
    __syncthreads();
    float r = sred[0];
    __syncthreads();
    return r;
}

// ---------------- chunk consume ----------------
// R rows of L floats in the slot; 16/R warps per row; warp reduces its piece.
template<int R, int L, class Fin>
__device__ __forceinline__ void consume_body(const float4* __restrict__ w4s,
                                             const float4* __restrict__ v4,
                                             int rows_eff, float* spart_buf, Fin fin) {
    const int tid = threadIdx.x;
    const int lane = tid & 31, wid = tid >> 5;
    constexpr int PW  = NWP / R;        // warps per row
    constexpr int PF4 = L / (4 * PW);   // float4 per piece
    constexpr int NK  = PF4 / 32;       // float4 per lane
    int row = wid / PW, sub = wid % PW;
    float acc = 0.f;
    if (row < rows_eff) {
        const float4* wr = w4s + row * (L / 4) + sub * PF4;
        const float4* vr = v4 + sub * PF4;
        #pragma unroll
        for (int k = 0; k < NK; k++) {
            float4 a = wr[k * 32 + lane];
            float4 b = vr[k * 32 + lane];
            acc = fmaf(a.x, b.x, acc); acc = fmaf(a.y, b.y, acc);
            acc = fmaf(a.z, b.z, acc); acc = fmaf(a.w, b.w, acc);
        }
    }
    #pragma unroll
    for (int o = 16; o; o >>= 1) acc += __shfl_xor_sync(0xffffffffu, acc, o);
    if (lane == 0) spart_buf[wid] = acc;
    __syncthreads();
    if (tid < R && tid < rows_eff) {
        float s = 0.f;
        #pragma unroll
        for (int q = 0; q < PW; q++) s += spart_buf[tid * PW + q];
        fin(tid, s);
    }
}

__global__ __launch_bounds__(NT, 1) void rwkv_persistent(
    const int*   __restrict__ ctx,
    const float* __restrict__ st_in,
    const float* __restrict__ emb,
    const float* __restrict__ ln0,
    const float* __restrict__ ln1,
    const float* __restrict__ ln2,
    const float* __restrict__ lnout,
    const float* __restrict__ tmk,
    const float* __restrict__ tmv,
    const float* __restrict__ tmr,
    const float* __restrict__ tfirst,
    const float* __restrict__ tdecay,
    const float* __restrict__ kw,
    const float* __restrict__ vw,
    const float* __restrict__ rw,
    const float* __restrict__ ow,
    const float* __restrict__ ftmk,
    const float* __restrict__ ftmr,
    const float* __restrict__ fkw,
    const float* __restrict__ fvw,
    const float* __restrict__ frw,
    const float* __restrict__ head,
    float* __restrict__ out,
    int nb)
{
    extern __shared__ float4 ring[];                 // S_RING * SLOT_F4
    __shared__ unsigned long long mbar[S_RING];
    __shared__ float vecS[3 * D];
    __shared__ float spart[2][NWP];
    __shared__ float sred[NWP];

    const int tid = threadIdx.x;
    const int bid = blockIdx.x;

    if (tid == 0) {
        #pragma unroll
        for (int s = 0; s < S_RING; s++) {
            unsigned a = (unsigned)__cvta_generic_to_shared(&mbar[s]);
            asm volatile("mbarrier.init.shared.b64 [%0], 1;" :: "r"(a));
        }
    }
    __syncthreads();

    int issued = 0, consumed = 0;

    // issue one chunk into the ring (tid 0 only; counters uniform)
    auto issue_to = [&](const float* gptr, int bytes) {
        int slot = issued % S_RING;
        if (tid == 0) {
            unsigned mb = (unsigned)__cvta_generic_to_shared(&mbar[slot]);
            unsigned sd = (unsigned)__cvta_generic_to_shared(ring + slot * SLOT_F4);
            asm volatile("mbarrier.arrive.expect_tx.shared.b64 _, [%0], %1;"
                         :: "r"(mb), "r"(bytes) : "memory");
            asm volatile("cp.async.bulk.shared::cta.global.mbarrier::complete_tx::bytes "
                         "[%0], [%1], %2, [%3];"
                         :: "r"(sd), "l"(gptr), "r"(bytes), "r"(mb) : "memory");
        }
        issued++;
    };

    auto top_up = [&](int& i_iss, int nmy, auto pb) {
        while (i_iss < nmy && issued - consumed < S_RING) {
            const float* p; int by;
            pb(i_iss, p, by);
            issue_to(p, by);
            i_iss++;
        }
    };

    auto ring_wait = [&]() -> const float4* {
        int slot = consumed % S_RING;
        unsigned ph = (unsigned)((consumed / S_RING) & 1);
        unsigned mb = (unsigned)__cvta_generic_to_shared(&mbar[slot]);
        unsigned done = 0;
        while (!done) {
            asm volatile("{\n\t.reg .pred p;\n\t"
                         "mbarrier.try_wait.parity.acquire.cta.shared::cta.b64 p, [%1], %2, 0x989680;\n\t"
                         "selp.b32 %0,1,0,p;\n\t}"
                         : "=r"(done) : "r"(mb), "r"(ph) : "memory");
        }
        return (const float4*)(ring + slot * SLOT_F4);
    };

    auto nmy_of = [&](int NC) { return bid < NC ? (NC - 1 - bid) / nb + 1 : 0; };
    const int nA = nmy_of(NC_A);
    const int nB = nmy_of(NC_B);
    const int nC = nmy_of(NC_C);
    const int nD = nmy_of(NC_D);
    const int nH = nmy_of(NC_H);

    float* out_logits = out;
    float* out_state  = out + VOCAB;
    const float4* vecS4 = (const float4*)vecS;

    // mutable weight pointers used by the issue lambdas (set before pre-issue)
    const float *kwl = kw, *vwl = vw, *rwl = rw;
    const float *owl = ow, *fkwl = fkw, *frwl = frw, *fvwl = fvw;

    auto pbA = [&](int i, const float*& p, int& by) {
        int c = bid + i * nb;
        int m = c >> 8; int lb = (c & 255) * 4;
        const float* base = (m == 0) ? kwl : ((m == 1) ? vwl : rwl);
        p = base + (size_t)lb * D; by = SLOT_B;
    };
    auto pbB = [&](int i, const float*& p, int& by) {
        int c = bid + i * nb;
        p = owl + (size_t)c * 2 * D; by = 8192;
    };
    auto pbC = [&](int i, const float*& p, int& by) {
        int c = bid + i * nb;
        p = (c < 1024) ? (fkwl + (size_t)c * 4 * D)
                       : (frwl + (size_t)(c - 1024) * 4 * D);
        by = SLOT_B;
    };
    auto pbD = [&](int i, const float*& p, int& by) {
        int c = bid + i * nb;
        p = fvwl + (size_t)c * HD; by = SLOT_B;
    };
    auto pbH = [&](int i, const float*& p, int& by) {
        int c = bid + i * nb;
        p = head + (size_t)c * 4 * D;
        int re = VOCAB - c * 4; if (re > 4) re = 4;
        by = re * 4096;
    };

    // ---------- pre-issue layer-0 stage A, compute embedding ----------
    int iA = 0, iB = 0, iC = 0, iD = 0, iH = 0;
    top_up(iA, nA, pbA);

    if (bid == 0) {
        const float* e = emb + (size_t)ctx[0] * D;
        float ss = 0.f;
        for (int j = tid; j < D; j += NT) { float t = e[j]; ss += t * t; }
        ss = block_sum(ss, sred);
        float inv = rsqrtf(ss * (1.f / D) + 1e-5f);
        for (int j = tid; j < D; j += NT) g_x[j] = e[j] * inv * ln0[j];
    }
    grid_barrier(nb);

    for (int l = 0; l < LNUM; l++) {
        const float* st_l  = st_in     + (size_t)l * 5 * D;
        float*       ost_l = out_state + (size_t)l * 5 * D;

        // ---------- stage A prep + consume (k/v/r) ----------
        {
            float ss = 0.f;
            for (int j = tid; j < D; j += NT) { float t = g_x[j]; ss += t * t; }
            ss = block_sum(ss, sred);
            float inv = rsqrtf(ss * (1.f / D) + 1e-5f);
            const float* l1 = ln1 + l * D;
            const float* mk = tmk + l * D;
            const float* mv = tmv + l * D;
            const float* mr = tmr + l * D;
            for (int j = tid; j < D; j += NT) {
                float xxj = g_x[j] * inv * l1[j];
                float sa  = st_l[D + j];
                float a_ = mk[j]; vecS[j]         = xxj * a_ + sa * (1.f - a_);
                float b_ = mv[j]; vecS[D + j]     = xxj * b_ + sa * (1.f - b_);
                float c_ = mr[j]; vecS[2 * D + j] = xxj * c_ + sa * (1.f - c_);
                if (bid == 0) ost_l[D + j] = xxj;
            }
            __syncthreads();
            for (int i = 0; i < nA; i++) {
                top_up(iA, nA, pbA);
                const float4* w4 = ring_wait();
                int c = bid + i * nb;
                int m = c >> 8;
                auto fin = [&](int r, float t) {
                    int row = c * 4 + r;
                    if (row < D)          g_k[row] = t;
                    else if (row < 2 * D) g_v[row - D] = t;
                    else                  g_r[row - 2 * D] = t;
                };
                consume_body<4, D>(w4, vecS4 + m * 256, 4, spart[i & 1], fin);
                consumed++;
            }
        }
        owl = ow + (size_t)l * D * D;
        iB = 0; top_up(iB, nB, pbB);
        grid_barrier(nb);

        // ---------- stage B prep (WKV) + consume (ow) ----------
        {
            const float* tfl = tfirst + l * D;
            const float* tdl = tdecay + l * D;
            for (int j = tid; j < D; j += NT) {
                float k  = g_k[j], v = g_v[j], rr = g_r[j];
                float aa = st_l[2 * D + j], bb = st_l[3 * D + j], pp = st_l[4 * D + j];
                float ww = tfl[j] + k;
                float p  = fmaxf(pp, ww);
                float e1 = __expf(pp - p), e2 = __expf(ww - p);
                float a  = e1 * aa + e2 * v;
                float b  = e1 * bb + e2;
                float sr = 1.f / (1.f + __expf(-rr));
                vecS[j] = sr * (a / b);
                if (bid == 0) {
                    float ww2 = pp + tdl[j];
                    float p2  = fmaxf(ww2, k);
                    float e1b = __expf(ww2 - p2), e2b = __expf(k - p2);
                    ost_l[2 * D + j] = e1b * aa + e2b * v;
                    ost_l[3 * D + j] = e1b * bb + e2b;
                    ost_l[4 * D + j] = p2;
                }
            }
            __syncthreads();
            for (int i = 0; i < nB; i++) {
                top_up(iB, nB, pbB);
                const float4* w4 = ring_wait();
                int c = bid + i * nb;
                auto fin = [&](int r, float t) { g_x[c * 2 + r] += t; };
                consume_body<2, D>(w4, vecS4, 2, spart[i & 1], fin);
                consumed++;
            }
        }
        fkwl = fkw + (size_t)l * HD * D;
        frwl = frw + (size_t)l * D * D;
        iC = 0; top_up(iC, nC, pbC);
        grid_barrier(nb);

        // ---------- stage C prep + consume (fkw / frw) ----------
        {
            float ss = 0.f;
            for (int j = tid; j < D; j += NT) { float t = g_x[j]; ss += t * t; }
            ss = block_sum(ss, sred);
            float inv = rsqrtf(ss * (1.f / D) + 1e-5f);
            const float* l2l = ln2  + l * D;
            const float* fmk = ftmk + l * D;
            const float* fmr = ftmr + l * D;
            for (int j = tid; j < D; j += NT) {
                float yyj = g_x[j] * inv * l2l[j];
                float ff  = st_l[j];
                float a_ = fmk[j]; vecS[j]     = yyj * a_ + ff * (1.f - a_);
                float b_ = fmr[j]; vecS[D + j] = yyj * b_ + ff * (1.f - b_);
                if (bid == 0) ost_l[j] = yyj;
            }
            __syncthreads();
            for (int i = 0; i < nC; i++) {
                top_up(iC, nC, pbC);
                const float4* w4 = ring_wait();
                int c = bid + i * nb;
                const float4* v4 = (c < 1024) ? vecS4 : (vecS4 + 256);
                auto fin = [&](int r, float t) {
                    if (c < 1024) {
                        t = fmaxf(t, 0.f);
                        g_k2[c * 4 + r] = t * t;
                    } else {
                        g_r2[(c - 1024) * 4 + r] = t;
                    }
                };
                consume_body<4, D>(w4, v4, 4, spart[i & 1], fin);
                consumed++;
            }
        }
        fvwl = fvw + (size_t)l * D * HD;
        iD = 0; top_up(iD, nD, pbD);
        grid_barrier(nb);

        // ---------- stage D consume (fvw, vec = g_k2 from L2) ----------
        {
            const float sc = ((l + 1) % 6 == 0) ? 0.5f : 1.0f;
            for (int i = 0; i < nD; i++) {
                top_up(iD, nD, pbD);
                const float4* w4 = ring_wait();
                int c = bid + i * nb;
                auto fin = [&](int r, float t) {
                    float sr = 1.f / (1.f + __expf(-g_r2[c]));
                    g_x[c] = (g_x[c] + sr * t) * sc;
                };
                consume_body<1, HD>(w4, (const float4*)g_k2, 1, spart[i & 1], fin);
                consumed++;
            }
        }
        if (l < LNUM - 1) {
            kwl = kw + (size_t)(l + 1) * D * D;
            vwl = vw + (size_t)(l + 1) * D * D;
            rwl = rw + (size_t)(l + 1) * D * D;
            iA = 0; top_up(iA, nA, pbA);
        } else {
            iH = 0; top_up(iH, nH, pbH);
        }
        grid_barrier(nb);
    }

    // ---------- head ----------
    {
        float ss = 0.f;
        for (int j = tid; j < D; j += NT) { float t = g_x[j]; ss += t * t; }
        ss = block_sum(ss, sred);
        float inv = rsqrtf(ss * (1.f / D) + 1e-5f);
        for (int j = tid; j < D; j += NT) vecS[j] = g_x[j] * inv * lnout[j];
        __syncthreads();
        for (int i = 0; i < nH; i++) {
            top_up(iH, nH, pbH);
            const float4* w4 = ring_wait();
            int c = bid + i * nb;
            int re = VOCAB - c * 4; if (re > 4) re = 4;
            auto fin = [&](int r, float t) { out_logits[c * 4 + r] = t; };
            consume_body<4, D>(w4, vecS4, re, spart[i & 1], fin);
            consumed++;
        }
    }
}

extern "C" void kernel_launch(void* const* d_in, const int* in_sizes, int n_in,
                              void* d_out, int out_size) {
    (void)in_sizes; (void)n_in; (void)out_size;
    int nb = 0;
    cudaDeviceGetAttribute(&nb, cudaDevAttrMultiProcessorCount, 0);
    if (nb <= 0) nb = 148;
    if (nb > 1024) nb = 1024;

    const int smem_bytes = S_RING * SLOT_B;
    cudaFuncSetAttribute(rwkv_persistent,
                         cudaFuncAttributeMaxDynamicSharedMemorySize, smem_bytes);

    rwkv_persistent<<<nb, NT, smem_bytes>>>(
        (const int*)  d_in[0],   // ctx
        (const float*)d_in[1],   // state
        (const float*)d_in[2],   // emb
        (const float*)d_in[3],   // ln0_w
        (const float*)d_in[4],   // ln1_w
        (const float*)d_in[5],   // ln2_w
        (const float*)d_in[6],   // lnout_w
        (const float*)d_in[7],   // att_tmk
        (const float*)d_in[8],   // att_tmv
        (const float*)d_in[9],   // att_tmr
        (const float*)d_in[10],  // att_tfirst
        (const float*)d_in[11],  // att_tdecay
        (const float*)d_in[12],  // att_kw
        (const float*)d_in[13],  // att_vw
        (const float*)d_in[14],  // att_rw
        (const float*)d_in[15],  // att_ow
        (const float*)d_in[16],  // ffn_tmk
        (const float*)d_in[17],  // ffn_tmr
        (const float*)d_in[18],  // ffn_kw
        (const float*)d_in[19],  // ffn_vw
        (const float*)d_in[20],  // ffn_rw
        (const float*)d_in[21],  // head
        (float*)d_out, nb);
}